// round 12
// baseline (speedup 1.0000x reference)
#include <cuda_runtime.h>
#include <cuda_bf16.h>
#include <cstdint>

// Problem constants
#define BATCH 4
#define SEQ   2048
#define HID   768
#define NHEAD 12
#define HDIM  64
#define QKV3  2304
#define KDIM  768

// Scratch (allocation-free: __device__ globals)
__device__ float g_qkv[(long)BATCH * SEQ * QKV3];    // [B,S,3H] tf32-rounded
__device__ float g_attn[(long)BATCH * SEQ * HID];    // [B,S,H]  tf32-rounded
__device__ float g_wqkvT[(long)QKV3 * KDIM];         // w_qkv tf32-rounded, [N][K]
__device__ float g_woutT[(long)HID * KDIM];          // w_out tf32-rounded, [N][K]
__device__ float g_vt[(long)BATCH * NHEAD * HDIM * SEQ];  // V transposed [b][h][d][s]

// ---------------------------------------------------------------------------
// Helpers
// ---------------------------------------------------------------------------
__device__ __forceinline__ uint32_t smem_u32(const void* p) {
    uint32_t a;
    asm("{ .reg .u64 t; cvta.to.shared.u64 t, %1; cvt.u32.u64 %0, t; }" : "=r"(a) : "l"(p));
    return a;
}
__device__ __forceinline__ float cvt_tf32(float x) {
    float r;
    asm("cvt.rna.tf32.f32 %0, %1;" : "=f"(r) : "f"(x));
    return r;
}
__device__ __forceinline__ uint32_t cvt_tf32_u(uint32_t x) {
    return __float_as_uint(cvt_tf32(__uint_as_float(x)));
}
__device__ __forceinline__ float ex2f(float x) {
    float r;
    asm("ex2.approx.f32 %0, %1;" : "=f"(r) : "f"(x));
    return r;
}
__device__ __forceinline__ void cp16(uint32_t dst, const void* src) {
    asm volatile("cp.async.ca.shared.global [%0], [%1], 16;" :: "r"(dst), "l"(src) : "memory");
}
__device__ __forceinline__ void cp_commit() {
    asm volatile("cp.async.commit_group;" ::: "memory");
}
__device__ __forceinline__ void cp_wait1() {
    asm volatile("cp.async.wait_group 1;" ::: "memory");
}
__device__ __forceinline__ void cp_wait0() {
    asm volatile("cp.async.wait_group 0;" ::: "memory");
}
__device__ __forceinline__ void sts2(uint32_t addr, float x, float y) {
    asm volatile("st.shared.v2.f32 [%0], {%1, %2};" :: "r"(addr), "f"(x), "f"(y) : "memory");
}
__device__ __forceinline__ void ldsm4(uint32_t* r, uint32_t addr) {
    asm volatile("ldmatrix.sync.aligned.m8n8.x4.shared.b16 {%0,%1,%2,%3}, [%4];"
                 : "=r"(r[0]), "=r"(r[1]), "=r"(r[2]), "=r"(r[3]) : "r"(addr));
}
__device__ __forceinline__ void ldsm2(uint32_t* r, uint32_t addr) {
    asm volatile("ldmatrix.sync.aligned.m8n8.x2.shared.b16 {%0,%1}, [%2];"
                 : "=r"(r[0]), "=r"(r[1]) : "r"(addr));
}
__device__ __forceinline__ void mma_tf32(float* c, const uint32_t* a, const uint32_t* b) {
    asm volatile(
        "mma.sync.aligned.m16n8k8.row.col.f32.tf32.tf32.f32 "
        "{%0,%1,%2,%3}, {%4,%5,%6,%7}, {%8,%9}, {%0,%1,%2,%3};"
        : "+f"(c[0]), "+f"(c[1]), "+f"(c[2]), "+f"(c[3])
        : "r"(a[0]), "r"(a[1]), "r"(a[2]), "r"(a[3]), "r"(b[0]), "r"(b[1]));
}

// ---------------------------------------------------------------------------
// tf32 mma.sync GEMM v5: ldmatrix fragment loads; grid x=M-tile, y=N-tile so
// consecutive bids share the B tile (L1 reuse with cp.async.ca).
// CVTA: apply tf32 rounding to A fragments in registers (A passed raw).
// ROUND: tf32-round output.
// ---------------------------------------------------------------------------
#define AT_BYTES (128 * 36 * 4)   // 18432
#define STAGE_BYTES (2 * AT_BYTES)
#define GEMM_SMEM_BYTES (3 * STAGE_BYTES)   // 110592

template <bool ROUND, bool CVTA>
__global__ __launch_bounds__(256, 2)
void gemm_tf32(const float* __restrict__ A, const float* __restrict__ Bt,
               float* __restrict__ C, int M, int N, int K)
{
    extern __shared__ char smem[];
    const uint32_t sb = smem_u32(smem);

    const int tid = threadIdx.x;
    const int wid = tid >> 5, lane = tid & 31;
    const int g = lane >> 2, l4 = lane & 3;
    const int warpM = wid >> 2, warpN = wid & 3;
    const int m0 = blockIdx.x * 128, n0 = blockIdx.y * 128;

    const int r = tid >> 1;
    const int h = (tid & 1) * 64;

    const float* Ag = A + (long)(m0 + r) * K + (h >> 2);
    const float* Bg = Bt + (long)(n0 + r) * K + (h >> 2);
    const int nch = K / 32;

    float c[4][4][4];
    #pragma unroll
    for (int mt = 0; mt < 4; mt++)
        #pragma unroll
        for (int nt = 0; nt < 4; nt++)
            #pragma unroll
            for (int q = 0; q < 4; q++) c[mt][nt][q] = 0.f;

    auto issue = [&](int chunk, int s) {
        const int k0 = chunk * 32;
        const uint32_t stage = sb + (uint32_t)s * STAGE_BYTES;
        const uint32_t dst = stage + r * 144 + h;
        const float* asrc = Ag + k0;
        #pragma unroll
        for (int q = 0; q < 4; q++) cp16(dst + q * 16, asrc + q * 4);
        const float* bsrc = Bg + k0;
        #pragma unroll
        for (int q = 0; q < 4; q++) cp16(dst + AT_BYTES + q * 16, bsrc + q * 4);
    };

    issue(0, 0); cp_commit();
    issue(1, 1); cp_commit();

    const int rlm = lane & 15, half = (lane >> 4) * 16;
    const int nr = lane & 7, sel = ((lane >> 3) & 1) * 16;
    const uint32_t aoff = (uint32_t)((warpM * 64 + rlm) * 144 + half);
    const uint32_t boff = (uint32_t)(AT_BYTES + (warpN * 32 + nr) * 144 + sel);

    #pragma unroll 1
    for (int i = 0; i < nch; i++) {
        const int s = i - (i / 3) * 3;
        if (i + 1 < nch) cp_wait1(); else cp_wait0();
        __syncthreads();
        if (i + 2 < nch) { issue(i + 2, (i + 2) % 3); cp_commit(); }

        const uint32_t abase = sb + (uint32_t)s * STAGE_BYTES + aoff;
        const uint32_t bbase = sb + (uint32_t)s * STAGE_BYTES + boff;

        #pragma unroll
        for (int ks = 0; ks < 4; ks++) {
            uint32_t af[4][4], bf[4][2];
            #pragma unroll
            for (int mt = 0; mt < 4; mt++) {
                ldsm4(af[mt], abase + mt * (16 * 144) + ks * 32);
                if (CVTA) {
                    af[mt][0] = cvt_tf32_u(af[mt][0]);
                    af[mt][1] = cvt_tf32_u(af[mt][1]);
                    af[mt][2] = cvt_tf32_u(af[mt][2]);
                    af[mt][3] = cvt_tf32_u(af[mt][3]);
                }
            }
            #pragma unroll
            for (int nt = 0; nt < 4; nt++)
                ldsm2(bf[nt], bbase + nt * (8 * 144) + ks * 32);
            #pragma unroll
            for (int mt = 0; mt < 4; mt++)
                #pragma unroll
                for (int nt = 0; nt < 4; nt++)
                    mma_tf32(c[mt][nt], af[mt], bf[nt]);
        }
    }

    #pragma unroll
    for (int mt = 0; mt < 4; mt++) {
        #pragma unroll
        for (int nt = 0; nt < 4; nt++) {
            const long row0 = (long)(m0 + warpM * 64 + mt * 16 + g);
            const int col = n0 + warpN * 32 + nt * 8 + l4 * 2;
            float v0 = c[mt][nt][0], v1 = c[mt][nt][1];
            float v2 = c[mt][nt][2], v3 = c[mt][nt][3];
            if (ROUND) {
                v0 = cvt_tf32(v0); v1 = cvt_tf32(v1);
                v2 = cvt_tf32(v2); v3 = cvt_tf32(v3);
            }
            *(float2*)&C[row0 * N + col] = make_float2(v0, v1);
            *(float2*)&C[(row0 + 8) * N + col] = make_float2(v2, v3);
        }
    }
}

// ---------------------------------------------------------------------------
// Prep kernels
// ---------------------------------------------------------------------------
// out[c][r] = tf32(in[r][c]).  in: [R][C] row-major, out: [C][R] row-major.
__global__ void transpose_tf32(const float* __restrict__ in, float* __restrict__ out,
                               int R, int C)
{
    __shared__ float tile[32][33];
    const int c0 = blockIdx.x * 32, r0 = blockIdx.y * 32;
    const int tx = threadIdx.x, ty = threadIdx.y;
    #pragma unroll
    for (int j = ty; j < 32; j += 8)
        tile[j][tx] = in[(long)(r0 + j) * C + c0 + tx];
    __syncthreads();
    #pragma unroll
    for (int j = ty; j < 32; j += 8)
        out[(long)(c0 + j) * R + r0 + tx] = cvt_tf32(tile[tx][j]);
}

// V slice of qkv -> vt[b][h][d][s]  (values already tf32-rounded)
__global__ void transpose_v(const float* __restrict__ qkv, float* __restrict__ vt)
{
    __shared__ float tile[32][33];
    const int bh = blockIdx.z;
    const int b = bh / NHEAD, hh = bh % NHEAD;
    const float* in = qkv + (long)b * SEQ * QKV3 + 2 * HID + hh * HDIM;
    float* out = vt + (long)bh * HDIM * SEQ;
    const int c0 = blockIdx.x * 32, r0 = blockIdx.y * 32;   // c: dim, r: seq
    const int tx = threadIdx.x, ty = threadIdx.y;
    #pragma unroll
    for (int j = ty; j < 32; j += 8)
        tile[j][tx] = in[(long)(r0 + j) * QKV3 + c0 + tx];
    __syncthreads();
    #pragma unroll
    for (int j = ty; j < 32; j += 8)
        out[(long)(c0 + j) * SEQ + r0 + tx] = tile[tx][j];
}

// ---------------------------------------------------------------------------
// Flash attention (causal) on tf32 mma.sync — R11 version (passing), unchanged.
// ---------------------------------------------------------------------------
#define FQT 128
#define FKT 64
#define KP 68
#define VP 68
#define PP 68
#define KS_OFF(s)  ((s) * 17408)
#define VS_OFF(s)  (34816 + (s) * 17408)
#define PS_OFF     69632
#define FLASH_SMEM_BYTES (PS_OFF + 128 * PP * 4)   // 104448
#define SC2 0.1803368801f   // (1/sqrt(64)) * log2(e)

__global__ __launch_bounds__(256)
void flash_tf32(const float* __restrict__ qkv, const float* __restrict__ vt,
                float* __restrict__ out)
{
    extern __shared__ char sm[];
    const uint32_t sb = smem_u32(sm);
    const int tid = threadIdx.x, w = tid >> 5, lane = tid & 31;
    const int g = lane >> 2, l4 = lane & 3;
    const int qt = (int)(gridDim.x - 1) - (int)blockIdx.x;
    const int hh = blockIdx.y, b = blockIdx.z;
    const int q0 = qt * FQT;
    const int nkv = 2 * qt + 2;

    const float* qg = qkv + (long)b * SEQ * QKV3 + hh * HDIM;
    const float* kg = qg + HID;
    const float* vtg = vt + (long)(b * NHEAD + hh) * HDIM * SEQ;

    const int rlm = lane & 15, half = (lane >> 4) * 16;
    const int nr = lane & 7, sel = ((lane >> 3) & 1) * 16;

    {
        const int r = tid >> 1, h2 = tid & 1;
        const float* src = qg + (long)(q0 + r) * QKV3 + h2 * 32;
        uint32_t dst = sb + PS_OFF + (uint32_t)(r * PP + h2 * 32) * 4;
        #pragma unroll
        for (int q = 0; q < 8; q++) cp16(dst + q * 16, src + q * 4);
        cp_commit();
    }
    cp_wait0();
    __syncthreads();

    uint32_t qa[8][4];
    #pragma unroll
    for (int ks = 0; ks < 8; ks++)
        ldsm4(qa[ks], sb + PS_OFF + (uint32_t)((w * 16 + rlm) * PP) * 4
                      + ks * 32 + half);
    __syncthreads();

    auto issue_kv = [&](int kt2, int s) {
        const int k0 = kt2 * FKT;
        const int r = tid >> 2, q4 = tid & 3;
        const float* ksrc = kg + (long)(k0 + r) * QKV3 + q4 * 16;
        uint32_t kdst = sb + KS_OFF(s) + (uint32_t)(r * KP + q4 * 16) * 4;
        #pragma unroll
        for (int q = 0; q < 4; q++) cp16(kdst + q * 16, ksrc + q * 4);
        const float* vsrc = vtg + (long)r * SEQ + k0 + q4 * 16;
        uint32_t vdst = sb + VS_OFF(s) + (uint32_t)(r * VP + q4 * 16) * 4;
        #pragma unroll
        for (int q = 0; q < 4; q++) cp16(vdst + q * 16, vsrc + q * 4);
    };

    issue_kv(0, 0); cp_commit();
    if (nkv > 1) issue_kv(1, 1);
    cp_commit();

    float mA = -1e30f, mB = -1e30f, lA = 0.f, lB = 0.f;
    float o[8][4];
    #pragma unroll
    for (int nt = 0; nt < 8; nt++)
        #pragma unroll
        for (int q = 0; q < 4; q++) o[nt][q] = 0.f;

    const int wrow0 = q0 + w * 16;

    #pragma unroll 1
    for (int kt = 0; kt < nkv; kt++) {
        const int s = kt & 1;
        if (kt + 2 < nkv) cp_wait1(); else cp_wait0();
        __syncthreads();

        const int k0 = kt * FKT;
        const bool active = (k0 <= wrow0 + 15);
        const bool needmask = (k0 + FKT - 1 > wrow0);

        if (active) {
            const uint32_t kb = sb + KS_OFF(s);
            const uint32_t vb = sb + VS_OFF(s);

            float cc[8][4];
            #pragma unroll
            for (int nt = 0; nt < 8; nt++)
                #pragma unroll
                for (int q = 0; q < 4; q++) cc[nt][q] = 0.f;

            #pragma unroll
            for (int ks = 0; ks < 8; ks++) {
                uint32_t bfr[8][2];
                #pragma unroll
                for (int nt = 0; nt < 8; nt++)
                    ldsm2(bfr[nt], kb + (uint32_t)((nt * 8 + nr) * KP) * 4
                                   + ks * 32 + sel);
                #pragma unroll
                for (int nt = 0; nt < 8; nt++)
                    mma_tf32(cc[nt], qa[ks], bfr[nt]);
            }

            const int rowA = wrow0 + g;
            if (needmask) {
                #pragma unroll
                for (int nt = 0; nt < 8; nt++) {
                    const int colb = k0 + nt * 8 + 2 * l4;
                    if (colb     > rowA)     cc[nt][0] = -1e30f;
                    if (colb + 1 > rowA)     cc[nt][1] = -1e30f;
                    if (colb     > rowA + 8) cc[nt][2] = -1e30f;
                    if (colb + 1 > rowA + 8) cc[nt][3] = -1e30f;
                }
            }

            float mxA = -1e30f, mxB = -1e30f;
            #pragma unroll
            for (int nt = 0; nt < 8; nt++) {
                mxA = fmaxf(mxA, fmaxf(cc[nt][0], cc[nt][1]));
                mxB = fmaxf(mxB, fmaxf(cc[nt][2], cc[nt][3]));
            }
            mxA = fmaxf(mxA, __shfl_xor_sync(0xffffffffu, mxA, 1));
            mxA = fmaxf(mxA, __shfl_xor_sync(0xffffffffu, mxA, 2));
            mxB = fmaxf(mxB, __shfl_xor_sync(0xffffffffu, mxB, 1));
            mxB = fmaxf(mxB, __shfl_xor_sync(0xffffffffu, mxB, 2));

            const float mAn = fmaxf(mA, mxA);
            const float mBn = fmaxf(mB, mxB);
            const float aAl = ex2f((mA - mAn) * SC2);
            const float aBl = ex2f((mB - mBn) * SC2);
            mA = mAn; mB = mBn;

            float sA = 0.f, sB = 0.f;
            const uint32_t pbase = sb + PS_OFF
                + (uint32_t)((w * 16 + g) * PP + 2 * l4) * 4;
            #pragma unroll
            for (int nt = 0; nt < 8; nt++) {
                float p0 = ex2f((cc[nt][0] - mAn) * SC2);
                float p1 = ex2f((cc[nt][1] - mAn) * SC2);
                float p2 = ex2f((cc[nt][2] - mBn) * SC2);
                float p3 = ex2f((cc[nt][3] - mBn) * SC2);
                sA += p0 + p1; sB += p2 + p3;
                sts2(pbase + nt * 32, cvt_tf32(p0), cvt_tf32(p1));
                sts2(pbase + nt * 32 + 8 * PP * 4, cvt_tf32(p2), cvt_tf32(p3));
            }
            sA += __shfl_xor_sync(0xffffffffu, sA, 1);
            sA += __shfl_xor_sync(0xffffffffu, sA, 2);
            sB += __shfl_xor_sync(0xffffffffu, sB, 1);
            sB += __shfl_xor_sync(0xffffffffu, sB, 2);
            lA = lA * aAl + sA;
            lB = lB * aBl + sB;

            #pragma unroll
            for (int nt = 0; nt < 8; nt++) {
                o[nt][0] *= aAl; o[nt][1] *= aAl;
                o[nt][2] *= aBl; o[nt][3] *= aBl;
            }
            __syncwarp();

            #pragma unroll
            for (int ks = 0; ks < 8; ks++) {
                uint32_t pa[4];
                ldsm4(pa, sb + PS_OFF + (uint32_t)((w * 16 + rlm) * PP) * 4
                          + ks * 32 + half);
                uint32_t bv[8][2];
                #pragma unroll
                for (int nt = 0; nt < 8; nt++)
                    ldsm2(bv[nt], vb + (uint32_t)((nt * 8 + nr) * VP) * 4
                                  + ks * 32 + sel);
                #pragma unroll
                for (int nt = 0; nt < 8; nt++)
                    mma_tf32(o[nt], pa, bv[nt]);
            }
        }

        __syncthreads();
        if (kt + 2 < nkv) { issue_kv(kt + 2, s); cp_commit(); }
    }

    {
        const float invA = 1.f / lA;
        const float invB = 1.f / lB;
        const long rowA = (long)b * SEQ + q0 + w * 16 + g;
        #pragma unroll
        for (int nt = 0; nt < 8; nt++) {
            const int col = hh * HDIM + nt * 8 + 2 * l4;
            *(float2*)&out[rowA * HID + col] =
                make_float2(cvt_tf32(o[nt][0] * invA), cvt_tf32(o[nt][1] * invA));
            *(float2*)&out[(rowA + 8) * HID + col] =
                make_float2(cvt_tf32(o[nt][2] * invB), cvt_tf32(o[nt][3] * invB));
        }
    }
}

// ---------------------------------------------------------------------------
// Launch
// ---------------------------------------------------------------------------
extern "C" void kernel_launch(void* const* d_in, const int* in_sizes, int n_in,
                              void* d_out, int out_size)
{
    const float* x     = (const float*)d_in[0];
    const float* w_qkv = (const float*)d_in[1];
    const float* w_out = (const float*)d_in[2];
    float* out = (float*)d_out;

    float *qkv, *attn, *wqkvT, *woutT, *vt;
    cudaGetSymbolAddress((void**)&qkv, g_qkv);
    cudaGetSymbolAddress((void**)&attn, g_attn);
    cudaGetSymbolAddress((void**)&wqkvT, g_wqkvT);
    cudaGetSymbolAddress((void**)&woutT, g_woutT);
    cudaGetSymbolAddress((void**)&vt, g_vt);

    const int M = BATCH * SEQ;   // 8192

    // 0) prep: transpose+round weights to [N][K] (x rounding fused into GEMM)
    transpose_tf32<<<dim3(QKV3 / 32, KDIM / 32), dim3(32, 8)>>>(w_qkv, wqkvT,
                                                                KDIM, QKV3);
    transpose_tf32<<<dim3(HID / 32, KDIM / 32), dim3(32, 8)>>>(w_out, woutT,
                                                               KDIM, HID);

    cudaFuncSetAttribute(gemm_tf32<true, true>,
                         cudaFuncAttributeMaxDynamicSharedMemorySize, GEMM_SMEM_BYTES);
    cudaFuncSetAttribute(gemm_tf32<false, false>,
                         cudaFuncAttributeMaxDynamicSharedMemorySize, GEMM_SMEM_BYTES);
    cudaFuncSetAttribute(flash_tf32,
                         cudaFuncAttributeMaxDynamicSharedMemorySize, FLASH_SMEM_BYTES);

    // 1) QKV projection: A = raw x, rounded in-register (CVTA)
    gemm_tf32<true, true><<<dim3(M / 128, QKV3 / 128), 256, GEMM_SMEM_BYTES>>>(
        x, wqkvT, qkv, M, QKV3, KDIM);

    // 1b) V -> vt[b][h][d][s]
    transpose_v<<<dim3(HDIM / 32, SEQ / 32, BATCH * NHEAD), dim3(32, 8)>>>(qkv, vt);

    // 2) Causal flash attention
    flash_tf32<<<dim3(SEQ / FQT, NHEAD, BATCH), 256, FLASH_SMEM_BYTES>>>(qkv, vt, attn);

    // 3) Output projection (attn already tf32-rounded by flash epilogue)
    gemm_tf32<false, false><<<dim3(M / 128, HID / 128), 256, GEMM_SMEM_BYTES>>>(
        attn, woutT, out, M, HID, KDIM);
}

// round 15
// speedup vs baseline: 1.0314x; 1.0314x over previous
#include <cuda_runtime.h>
#include <cuda_bf16.h>
#include <cstdint>

// Problem constants
#define BATCH 4
#define SEQ   2048
#define HID   768
#define NHEAD 12
#define HDIM  64
#define QKV3  2304
#define KDIM  768

// Scratch (allocation-free: __device__ globals)
__device__ float g_qkv[(long)BATCH * SEQ * QKV3];    // [B,S,3H] tf32-rounded
__device__ float g_attn[(long)BATCH * SEQ * HID];    // [B,S,H]  tf32-rounded
__device__ float g_wqkvT[(long)QKV3 * KDIM];         // w_qkv tf32-rounded, [N][K]
__device__ float g_woutT[(long)HID * KDIM];          // w_out tf32-rounded, [N][K]
__device__ float g_vt[(long)BATCH * NHEAD * HDIM * SEQ];  // V transposed [b][h][d][s]

// ---------------------------------------------------------------------------
// Helpers
// ---------------------------------------------------------------------------
__device__ __forceinline__ uint32_t smem_u32(const void* p) {
    uint32_t a;
    asm("{ .reg .u64 t; cvta.to.shared.u64 t, %1; cvt.u32.u64 %0, t; }" : "=r"(a) : "l"(p));
    return a;
}
__device__ __forceinline__ float cvt_tf32(float x) {
    float r;
    asm("cvt.rna.tf32.f32 %0, %1;" : "=f"(r) : "f"(x));
    return r;
}
__device__ __forceinline__ uint32_t cvt_tf32_u(uint32_t x) {
    return __float_as_uint(cvt_tf32(__uint_as_float(x)));
}
__device__ __forceinline__ float ex2f(float x) {
    float r;
    asm("ex2.approx.f32 %0, %1;" : "=f"(r) : "f"(x));
    return r;
}
__device__ __forceinline__ void cp16(uint32_t dst, const void* src) {
    asm volatile("cp.async.cg.shared.global [%0], [%1], 16;" :: "r"(dst), "l"(src) : "memory");
}
__device__ __forceinline__ void cp_commit() {
    asm volatile("cp.async.commit_group;" ::: "memory");
}
__device__ __forceinline__ void cp_wait1() {
    asm volatile("cp.async.wait_group 1;" ::: "memory");
}
__device__ __forceinline__ void cp_wait0() {
    asm volatile("cp.async.wait_group 0;" ::: "memory");
}
__device__ __forceinline__ void sts2(uint32_t addr, float x, float y) {
    asm volatile("st.shared.v2.f32 [%0], {%1, %2};" :: "r"(addr), "f"(x), "f"(y) : "memory");
}
__device__ __forceinline__ void ldsm4(uint32_t* r, uint32_t addr) {
    asm volatile("ldmatrix.sync.aligned.m8n8.x4.shared.b16 {%0,%1,%2,%3}, [%4];"
                 : "=r"(r[0]), "=r"(r[1]), "=r"(r[2]), "=r"(r[3]) : "r"(addr));
}
__device__ __forceinline__ void ldsm2(uint32_t* r, uint32_t addr) {
    asm volatile("ldmatrix.sync.aligned.m8n8.x2.shared.b16 {%0,%1}, [%2];"
                 : "=r"(r[0]), "=r"(r[1]) : "r"(addr));
}
__device__ __forceinline__ void mma_tf32(float* c, const uint32_t* a, const uint32_t* b) {
    asm volatile(
        "mma.sync.aligned.m16n8k8.row.col.f32.tf32.tf32.f32 "
        "{%0,%1,%2,%3}, {%4,%5,%6,%7}, {%8,%9}, {%0,%1,%2,%3};"
        : "+f"(c[0]), "+f"(c[1]), "+f"(c[2]), "+f"(c[3])
        : "r"(a[0]), "r"(a[1]), "r"(a[2]), "r"(a[3]), "r"(b[0]), "r"(b[1]));
}

// ---------------------------------------------------------------------------
// tf32 mma.sync GEMM v6: R11 memory config (cp.async.cg, grid bx=N / by=M)
// + CVTA fusion (tf32-round A fragments in registers; A passed raw).
// ROUND: tf32-round output.
// ---------------------------------------------------------------------------
#define AT_BYTES (128 * 36 * 4)   // 18432
#define STAGE_BYTES (2 * AT_BYTES)
#define GEMM_SMEM_BYTES (3 * STAGE_BYTES)   // 110592

template <bool ROUND, bool CVTA>
__global__ __launch_bounds__(256, 2)
void gemm_tf32(const float* __restrict__ A, const float* __restrict__ Bt,
               float* __restrict__ C, int M, int N, int K)
{
    extern __shared__ char smem[];
    const uint32_t sb = smem_u32(smem);

    const int tid = threadIdx.x;
    const int wid = tid >> 5, lane = tid & 31;
    const int g = lane >> 2, l4 = lane & 3;
    const int warpM = wid >> 2, warpN = wid & 3;
    const int m0 = blockIdx.y * 128, n0 = blockIdx.x * 128;

    const int r = tid >> 1;
    const int h = (tid & 1) * 64;

    const float* Ag = A + (long)(m0 + r) * K + (h >> 2);
    const float* Bg = Bt + (long)(n0 + r) * K + (h >> 2);
    const int nch = K / 32;

    float c[4][4][4];
    #pragma unroll
    for (int mt = 0; mt < 4; mt++)
        #pragma unroll
        for (int nt = 0; nt < 4; nt++)
            #pragma unroll
            for (int q = 0; q < 4; q++) c[mt][nt][q] = 0.f;

    auto issue = [&](int chunk, int s) {
        const int k0 = chunk * 32;
        const uint32_t stage = sb + (uint32_t)s * STAGE_BYTES;
        const uint32_t dst = stage + r * 144 + h;
        const float* asrc = Ag + k0;
        #pragma unroll
        for (int q = 0; q < 4; q++) cp16(dst + q * 16, asrc + q * 4);
        const float* bsrc = Bg + k0;
        #pragma unroll
        for (int q = 0; q < 4; q++) cp16(dst + AT_BYTES + q * 16, bsrc + q * 4);
    };

    issue(0, 0); cp_commit();
    issue(1, 1); cp_commit();

    const int rlm = lane & 15, half = (lane >> 4) * 16;
    const int nr = lane & 7, sel = ((lane >> 3) & 1) * 16;
    const uint32_t aoff = (uint32_t)((warpM * 64 + rlm) * 144 + half);
    const uint32_t boff = (uint32_t)(AT_BYTES + (warpN * 32 + nr) * 144 + sel);

    #pragma unroll 1
    for (int i = 0; i < nch; i++) {
        const int s = i - (i / 3) * 3;
        if (i + 1 < nch) cp_wait1(); else cp_wait0();
        __syncthreads();
        if (i + 2 < nch) { issue(i + 2, (i + 2) % 3); cp_commit(); }

        const uint32_t abase = sb + (uint32_t)s * STAGE_BYTES + aoff;
        const uint32_t bbase = sb + (uint32_t)s * STAGE_BYTES + boff;

        #pragma unroll
        for (int ks = 0; ks < 4; ks++) {
            uint32_t af[4][4], bf[4][2];
            #pragma unroll
            for (int mt = 0; mt < 4; mt++) {
                ldsm4(af[mt], abase + mt * (16 * 144) + ks * 32);
                if (CVTA) {
                    af[mt][0] = cvt_tf32_u(af[mt][0]);
                    af[mt][1] = cvt_tf32_u(af[mt][1]);
                    af[mt][2] = cvt_tf32_u(af[mt][2]);
                    af[mt][3] = cvt_tf32_u(af[mt][3]);
                }
            }
            #pragma unroll
            for (int nt = 0; nt < 4; nt++)
                ldsm2(bf[nt], bbase + nt * (8 * 144) + ks * 32);
            #pragma unroll
            for (int mt = 0; mt < 4; mt++)
                #pragma unroll
                for (int nt = 0; nt < 4; nt++)
                    mma_tf32(c[mt][nt], af[mt], bf[nt]);
        }
    }

    #pragma unroll
    for (int mt = 0; mt < 4; mt++) {
        #pragma unroll
        for (int nt = 0; nt < 4; nt++) {
            const long row0 = (long)(m0 + warpM * 64 + mt * 16 + g);
            const int col = n0 + warpN * 32 + nt * 8 + l4 * 2;
            float v0 = c[mt][nt][0], v1 = c[mt][nt][1];
            float v2 = c[mt][nt][2], v3 = c[mt][nt][3];
            if (ROUND) {
                v0 = cvt_tf32(v0); v1 = cvt_tf32(v1);
                v2 = cvt_tf32(v2); v3 = cvt_tf32(v3);
            }
            *(float2*)&C[row0 * N + col] = make_float2(v0, v1);
            *(float2*)&C[(row0 + 8) * N + col] = make_float2(v2, v3);
        }
    }
}

// ---------------------------------------------------------------------------
// Prep kernels
// ---------------------------------------------------------------------------
// out[c][r] = tf32(in[r][c]).  in: [R][C] row-major, out: [C][R] row-major.
__global__ void transpose_tf32(const float* __restrict__ in, float* __restrict__ out,
                               int R, int C)
{
    __shared__ float tile[32][33];
    const int c0 = blockIdx.x * 32, r0 = blockIdx.y * 32;
    const int tx = threadIdx.x, ty = threadIdx.y;
    #pragma unroll
    for (int j = ty; j < 32; j += 8)
        tile[j][tx] = in[(long)(r0 + j) * C + c0 + tx];
    __syncthreads();
    #pragma unroll
    for (int j = ty; j < 32; j += 8)
        out[(long)(c0 + j) * R + r0 + tx] = cvt_tf32(tile[tx][j]);
}

// V slice of qkv -> vt[b][h][d][s]  (values already tf32-rounded)
__global__ void transpose_v(const float* __restrict__ qkv, float* __restrict__ vt)
{
    __shared__ float tile[32][33];
    const int bh = blockIdx.z;
    const int b = bh / NHEAD, hh = bh % NHEAD;
    const float* in = qkv + (long)b * SEQ * QKV3 + 2 * HID + hh * HDIM;
    float* out = vt + (long)bh * HDIM * SEQ;
    const int c0 = blockIdx.x * 32, r0 = blockIdx.y * 32;   // c: dim, r: seq
    const int tx = threadIdx.x, ty = threadIdx.y;
    #pragma unroll
    for (int j = ty; j < 32; j += 8)
        tile[j][tx] = in[(long)(r0 + j) * QKV3 + c0 + tx];
    __syncthreads();
    #pragma unroll
    for (int j = ty; j < 32; j += 8)
        out[(long)(c0 + j) * SEQ + r0 + tx] = tile[tx][j];
}

// ---------------------------------------------------------------------------
// Flash attention (causal) on tf32 mma.sync — R11 version (passing), unchanged.
// ---------------------------------------------------------------------------
#define FQT 128
#define FKT 64
#define KP 68
#define VP 68
#define PP 68
#define KS_OFF(s)  ((s) * 17408)
#define VS_OFF(s)  (34816 + (s) * 17408)
#define PS_OFF     69632
#define FLASH_SMEM_BYTES (PS_OFF + 128 * PP * 4)   // 104448
#define SC2 0.1803368801f   // (1/sqrt(64)) * log2(e)

__global__ __launch_bounds__(256)
void flash_tf32(const float* __restrict__ qkv, const float* __restrict__ vt,
                float* __restrict__ out)
{
    extern __shared__ char sm[];
    const uint32_t sb = smem_u32(sm);
    const int tid = threadIdx.x, w = tid >> 5, lane = tid & 31;
    const int g = lane >> 2, l4 = lane & 3;
    const int qt = (int)(gridDim.x - 1) - (int)blockIdx.x;
    const int hh = blockIdx.y, b = blockIdx.z;
    const int q0 = qt * FQT;
    const int nkv = 2 * qt + 2;

    const float* qg = qkv + (long)b * SEQ * QKV3 + hh * HDIM;
    const float* kg = qg + HID;
    const float* vtg = vt + (long)(b * NHEAD + hh) * HDIM * SEQ;

    const int rlm = lane & 15, half = (lane >> 4) * 16;
    const int nr = lane & 7, sel = ((lane >> 3) & 1) * 16;

    {
        const int r = tid >> 1, h2 = tid & 1;
        const float* src = qg + (long)(q0 + r) * QKV3 + h2 * 32;
        uint32_t dst = sb + PS_OFF + (uint32_t)(r * PP + h2 * 32) * 4;
        #pragma unroll
        for (int q = 0; q < 8; q++) cp16(dst + q * 16, src + q * 4);
        cp_commit();
    }
    cp_wait0();
    __syncthreads();

    uint32_t qa[8][4];
    #pragma unroll
    for (int ks = 0; ks < 8; ks++)
        ldsm4(qa[ks], sb + PS_OFF + (uint32_t)((w * 16 + rlm) * PP) * 4
                      + ks * 32 + half);
    __syncthreads();

    auto issue_kv = [&](int kt2, int s) {
        const int k0 = kt2 * FKT;
        const int r = tid >> 2, q4 = tid & 3;
        const float* ksrc = kg + (long)(k0 + r) * QKV3 + q4 * 16;
        uint32_t kdst = sb + KS_OFF(s) + (uint32_t)(r * KP + q4 * 16) * 4;
        #pragma unroll
        for (int q = 0; q < 4; q++) cp16(kdst + q * 16, ksrc + q * 4);
        const float* vsrc = vtg + (long)r * SEQ + k0 + q4 * 16;
        uint32_t vdst = sb + VS_OFF(s) + (uint32_t)(r * VP + q4 * 16) * 4;
        #pragma unroll
        for (int q = 0; q < 4; q++) cp16(vdst + q * 16, vsrc + q * 4);
    };

    issue_kv(0, 0); cp_commit();
    if (nkv > 1) issue_kv(1, 1);
    cp_commit();

    float mA = -1e30f, mB = -1e30f, lA = 0.f, lB = 0.f;
    float o[8][4];
    #pragma unroll
    for (int nt = 0; nt < 8; nt++)
        #pragma unroll
        for (int q = 0; q < 4; q++) o[nt][q] = 0.f;

    const int wrow0 = q0 + w * 16;

    #pragma unroll 1
    for (int kt = 0; kt < nkv; kt++) {
        const int s = kt & 1;
        if (kt + 2 < nkv) cp_wait1(); else cp_wait0();
        __syncthreads();

        const int k0 = kt * FKT;
        const bool active = (k0 <= wrow0 + 15);
        const bool needmask = (k0 + FKT - 1 > wrow0);

        if (active) {
            const uint32_t kb = sb + KS_OFF(s);
            const uint32_t vb = sb + VS_OFF(s);

            float cc[8][4];
            #pragma unroll
            for (int nt = 0; nt < 8; nt++)
                #pragma unroll
                for (int q = 0; q < 4; q++) cc[nt][q] = 0.f;

            #pragma unroll
            for (int ks = 0; ks < 8; ks++) {
                uint32_t bfr[8][2];
                #pragma unroll
                for (int nt = 0; nt < 8; nt++)
                    ldsm2(bfr[nt], kb + (uint32_t)((nt * 8 + nr) * KP) * 4
                                   + ks * 32 + sel);
                #pragma unroll
                for (int nt = 0; nt < 8; nt++)
                    mma_tf32(cc[nt], qa[ks], bfr[nt]);
            }

            const int rowA = wrow0 + g;
            if (needmask) {
                #pragma unroll
                for (int nt = 0; nt < 8; nt++) {
                    const int colb = k0 + nt * 8 + 2 * l4;
                    if (colb     > rowA)     cc[nt][0] = -1e30f;
                    if (colb + 1 > rowA)     cc[nt][1] = -1e30f;
                    if (colb     > rowA + 8) cc[nt][2] = -1e30f;
                    if (colb + 1 > rowA + 8) cc[nt][3] = -1e30f;
                }
            }

            float mxA = -1e30f, mxB = -1e30f;
            #pragma unroll
            for (int nt = 0; nt < 8; nt++) {
                mxA = fmaxf(mxA, fmaxf(cc[nt][0], cc[nt][1]));
                mxB = fmaxf(mxB, fmaxf(cc[nt][2], cc[nt][3]));
            }
            mxA = fmaxf(mxA, __shfl_xor_sync(0xffffffffu, mxA, 1));
            mxA = fmaxf(mxA, __shfl_xor_sync(0xffffffffu, mxA, 2));
            mxB = fmaxf(mxB, __shfl_xor_sync(0xffffffffu, mxB, 1));
            mxB = fmaxf(mxB, __shfl_xor_sync(0xffffffffu, mxB, 2));

            const float mAn = fmaxf(mA, mxA);
            const float mBn = fmaxf(mB, mxB);
            const float aAl = ex2f((mA - mAn) * SC2);
            const float aBl = ex2f((mB - mBn) * SC2);
            mA = mAn; mB = mBn;

            float sA = 0.f, sB = 0.f;
            const uint32_t pbase = sb + PS_OFF
                + (uint32_t)((w * 16 + g) * PP + 2 * l4) * 4;
            #pragma unroll
            for (int nt = 0; nt < 8; nt++) {
                float p0 = ex2f((cc[nt][0] - mAn) * SC2);
                float p1 = ex2f((cc[nt][1] - mAn) * SC2);
                float p2 = ex2f((cc[nt][2] - mBn) * SC2);
                float p3 = ex2f((cc[nt][3] - mBn) * SC2);
                sA += p0 + p1; sB += p2 + p3;
                sts2(pbase + nt * 32, cvt_tf32(p0), cvt_tf32(p1));
                sts2(pbase + nt * 32 + 8 * PP * 4, cvt_tf32(p2), cvt_tf32(p3));
            }
            sA += __shfl_xor_sync(0xffffffffu, sA, 1);
            sA += __shfl_xor_sync(0xffffffffu, sA, 2);
            sB += __shfl_xor_sync(0xffffffffu, sB, 1);
            sB += __shfl_xor_sync(0xffffffffu, sB, 2);
            lA = lA * aAl + sA;
            lB = lB * aBl + sB;

            #pragma unroll
            for (int nt = 0; nt < 8; nt++) {
                o[nt][0] *= aAl; o[nt][1] *= aAl;
                o[nt][2] *= aBl; o[nt][3] *= aBl;
            }
            __syncwarp();

            #pragma unroll
            for (int ks = 0; ks < 8; ks++) {
                uint32_t pa[4];
                ldsm4(pa, sb + PS_OFF + (uint32_t)((w * 16 + rlm) * PP) * 4
                          + ks * 32 + half);
                uint32_t bv[8][2];
                #pragma unroll
                for (int nt = 0; nt < 8; nt++)
                    ldsm2(bv[nt], vb + (uint32_t)((nt * 8 + nr) * VP) * 4
                                  + ks * 32 + sel);
                #pragma unroll
                for (int nt = 0; nt < 8; nt++)
                    mma_tf32(o[nt], pa, bv[nt]);
            }
        }

        __syncthreads();
        if (kt + 2 < nkv) { issue_kv(kt + 2, s); cp_commit(); }
    }

    {
        const float invA = 1.f / lA;
        const float invB = 1.f / lB;
        const long rowA = (long)b * SEQ + q0 + w * 16 + g;
        #pragma unroll
        for (int nt = 0; nt < 8; nt++) {
            const int col = hh * HDIM + nt * 8 + 2 * l4;
            *(float2*)&out[rowA * HID + col] =
                make_float2(cvt_tf32(o[nt][0] * invA), cvt_tf32(o[nt][1] * invA));
            *(float2*)&out[(rowA + 8) * HID + col] =
                make_float2(cvt_tf32(o[nt][2] * invB), cvt_tf32(o[nt][3] * invB));
        }
    }
}

// ---------------------------------------------------------------------------
// Launch
// ---------------------------------------------------------------------------
extern "C" void kernel_launch(void* const* d_in, const int* in_sizes, int n_in,
                              void* d_out, int out_size)
{
    const float* x     = (const float*)d_in[0];
    const float* w_qkv = (const float*)d_in[1];
    const float* w_out = (const float*)d_in[2];
    float* out = (float*)d_out;

    float *qkv, *attn, *wqkvT, *woutT, *vt;
    cudaGetSymbolAddress((void**)&qkv, g_qkv);
    cudaGetSymbolAddress((void**)&attn, g_attn);
    cudaGetSymbolAddress((void**)&wqkvT, g_wqkvT);
    cudaGetSymbolAddress((void**)&woutT, g_woutT);
    cudaGetSymbolAddress((void**)&vt, g_vt);

    const int M = BATCH * SEQ;   // 8192

    // 0) prep: transpose+round weights to [N][K] (x rounding fused into GEMM)
    transpose_tf32<<<dim3(QKV3 / 32, KDIM / 32), dim3(32, 8)>>>(w_qkv, wqkvT,
                                                                KDIM, QKV3);
    transpose_tf32<<<dim3(HID / 32, KDIM / 32), dim3(32, 8)>>>(w_out, woutT,
                                                               KDIM, HID);

    cudaFuncSetAttribute(gemm_tf32<true, true>,
                         cudaFuncAttributeMaxDynamicSharedMemorySize, GEMM_SMEM_BYTES);
    cudaFuncSetAttribute(gemm_tf32<false, false>,
                         cudaFuncAttributeMaxDynamicSharedMemorySize, GEMM_SMEM_BYTES);
    cudaFuncSetAttribute(flash_tf32,
                         cudaFuncAttributeMaxDynamicSharedMemorySize, FLASH_SMEM_BYTES);

    // 1) QKV projection: grid bx=N, by=M (matches kernel indexing)
    gemm_tf32<true, true><<<dim3(QKV3 / 128, M / 128), 256, GEMM_SMEM_BYTES>>>(
        x, wqkvT, qkv, M, QKV3, KDIM);

    // 1b) V -> vt[b][h][d][s]
    transpose_v<<<dim3(HDIM / 32, SEQ / 32, BATCH * NHEAD), dim3(32, 8)>>>(qkv, vt);

    // 2) Causal flash attention
    flash_tf32<<<dim3(SEQ / FQT, NHEAD, BATCH), 256, FLASH_SMEM_BYTES>>>(qkv, vt, attn);

    // 3) Output projection: grid bx=N, by=M (FIX: was swapped -> OOB)
    gemm_tf32<false, false><<<dim3(HID / 128, M / 128), 256, GEMM_SMEM_BYTES>>>(
        attn, woutT, out, M, HID, KDIM);
}

// round 16
// speedup vs baseline: 1.9381x; 1.8790x over previous
#include <cuda_runtime.h>
#include <cuda_fp16.h>
#include <cstdint>

// Problem constants
#define BATCH 4
#define SEQ   2048
#define HID   768
#define NHEAD 12
#define HDIM  64
#define QKV3  2304
#define KDIM  768

// Scratch (allocation-free: __device__ globals)
__device__ __half g_xh[(long)BATCH * SEQ * HID];          // x -> fp16
__device__ __half g_qkvh[(long)BATCH * SEQ * QKV3];       // qkv fp16
__device__ __half g_attnh[(long)BATCH * SEQ * HID];       // attention out fp16
__device__ __half g_wqkvT[(long)QKV3 * KDIM];             // w_qkv fp16 [N][K]
__device__ __half g_woutT[(long)HID * KDIM];              // w_out fp16 [N][K]
__device__ __half g_vt[(long)BATCH * NHEAD * HDIM * SEQ]; // V fp16 [b][h][d][s]

// ---------------------------------------------------------------------------
// Helpers
// ---------------------------------------------------------------------------
__device__ __forceinline__ uint32_t smem_u32(const void* p) {
    uint32_t a;
    asm("{ .reg .u64 t; cvta.to.shared.u64 t, %1; cvt.u32.u64 %0, t; }" : "=r"(a) : "l"(p));
    return a;
}
__device__ __forceinline__ float ex2f(float x) {
    float r;
    asm("ex2.approx.f32 %0, %1;" : "=f"(r) : "f"(x));
    return r;
}
__device__ __forceinline__ void cp16(uint32_t dst, const void* src) {
    asm volatile("cp.async.cg.shared.global [%0], [%1], 16;" :: "r"(dst), "l"(src) : "memory");
}
__device__ __forceinline__ void cp_commit() {
    asm volatile("cp.async.commit_group;" ::: "memory");
}
__device__ __forceinline__ void cp_wait1() {
    asm volatile("cp.async.wait_group 1;" ::: "memory");
}
__device__ __forceinline__ void cp_wait0() {
    asm volatile("cp.async.wait_group 0;" ::: "memory");
}
__device__ __forceinline__ void sts32(uint32_t addr, uint32_t v) {
    asm volatile("st.shared.b32 [%0], %1;" :: "r"(addr), "r"(v) : "memory");
}
__device__ __forceinline__ void ldsm4(uint32_t* r, uint32_t addr) {
    asm volatile("ldmatrix.sync.aligned.m8n8.x4.shared.b16 {%0,%1,%2,%3}, [%4];"
                 : "=r"(r[0]), "=r"(r[1]), "=r"(r[2]), "=r"(r[3]) : "r"(addr));
}
__device__ __forceinline__ void ldsm2(uint32_t* r, uint32_t addr) {
    asm volatile("ldmatrix.sync.aligned.m8n8.x2.shared.b16 {%0,%1}, [%2];"
                 : "=r"(r[0]), "=r"(r[1]) : "r"(addr));
}
__device__ __forceinline__ void mma_f16(float* c, const uint32_t* a, const uint32_t* b) {
    asm volatile(
        "mma.sync.aligned.m16n8k16.row.col.f32.f16.f16.f32 "
        "{%0,%1,%2,%3}, {%4,%5,%6,%7}, {%8,%9}, {%0,%1,%2,%3};"
        : "+f"(c[0]), "+f"(c[1]), "+f"(c[2]), "+f"(c[3])
        : "r"(a[0]), "r"(a[1]), "r"(a[2]), "r"(a[3]), "r"(b[0]), "r"(b[1]));
}
__device__ __forceinline__ uint32_t pack_h2(float a, float b) {
    __half2 h = __floats2half2_rn(a, b);
    return *reinterpret_cast<uint32_t*>(&h);
}

// ---------------------------------------------------------------------------
// fp16 mma.sync GEMM: C[M,N] = A[M,K] @ Bt[N,K]^T, A/Bt half.
// CTA 128x128, K chunk 64 (4 x k16), 3-stage cp.async, 8 warps (2Mx4N).
// SMEM per stage: A[128][144B] + B[128][144B] (72-half pitch, conflict-free).
// OUTH: write half output (qkv); else float (final out).
// ---------------------------------------------------------------------------
#define AT_BYTES (128 * 144)        // 18432
#define STAGE_BYTES (2 * AT_BYTES)  // 36864
#define GEMM_SMEM_BYTES (3 * STAGE_BYTES)   // 110592

template <bool OUTH>
__global__ __launch_bounds__(256, 2)
void gemm_f16(const __half* __restrict__ A, const __half* __restrict__ Bt,
              void* __restrict__ Cv, int M, int N, int K)
{
    extern __shared__ char smem[];
    const uint32_t sb = smem_u32(smem);

    const int tid = threadIdx.x;
    const int wid = tid >> 5, lane = tid & 31;
    const int g = lane >> 2, l4 = lane & 3;
    const int warpM = wid >> 2, warpN = wid & 3;
    const int m0 = blockIdx.y * 128, n0 = blockIdx.x * 128;

    const int r = tid >> 1;
    const int h = (tid & 1) * 64;   // byte offset within 128B row

    const __half* Ag = A + (long)(m0 + r) * K + (h >> 1);
    const __half* Bg = Bt + (long)(n0 + r) * K + (h >> 1);
    const int nch = K / 64;   // 12

    float c[4][4][4];
    #pragma unroll
    for (int mt = 0; mt < 4; mt++)
        #pragma unroll
        for (int nt = 0; nt < 4; nt++)
            #pragma unroll
            for (int q = 0; q < 4; q++) c[mt][nt][q] = 0.f;

    auto issue = [&](int chunk, int s) {
        const int k0 = chunk * 64;
        const uint32_t stage = sb + (uint32_t)s * STAGE_BYTES;
        const uint32_t dst = stage + r * 144 + h;
        const __half* asrc = Ag + k0;
        #pragma unroll
        for (int q = 0; q < 4; q++) cp16(dst + q * 16, asrc + q * 8);
        const __half* bsrc = Bg + k0;
        #pragma unroll
        for (int q = 0; q < 4; q++) cp16(dst + AT_BYTES + q * 16, bsrc + q * 8);
    };

    issue(0, 0); cp_commit();
    issue(1, 1); cp_commit();

    const int rlm = lane & 15, half_ = (lane >> 4) * 16;   // A x4
    const int nr = lane & 7, sel = ((lane >> 3) & 1) * 16; // B x2
    const uint32_t aoff = (uint32_t)((warpM * 64 + rlm) * 144 + half_);
    const uint32_t boff = (uint32_t)(AT_BYTES + (warpN * 32 + nr) * 144 + sel);

    #pragma unroll 1
    for (int i = 0; i < nch; i++) {
        const int s = i - (i / 3) * 3;
        if (i + 1 < nch) cp_wait1(); else cp_wait0();
        __syncthreads();
        if (i + 2 < nch) { issue(i + 2, (i + 2) % 3); cp_commit(); }

        const uint32_t abase = sb + (uint32_t)s * STAGE_BYTES + aoff;
        const uint32_t bbase = sb + (uint32_t)s * STAGE_BYTES + boff;

        #pragma unroll
        for (int ks = 0; ks < 4; ks++) {
            uint32_t af[4][4], bf[4][2];
            #pragma unroll
            for (int mt = 0; mt < 4; mt++)
                ldsm4(af[mt], abase + mt * (16 * 144) + ks * 32);
            #pragma unroll
            for (int nt = 0; nt < 4; nt++)
                ldsm2(bf[nt], bbase + nt * (8 * 144) + ks * 32);
            #pragma unroll
            for (int mt = 0; mt < 4; mt++)
                #pragma unroll
                for (int nt = 0; nt < 4; nt++)
                    mma_f16(c[mt][nt], af[mt], bf[nt]);
        }
    }

    #pragma unroll
    for (int mt = 0; mt < 4; mt++) {
        #pragma unroll
        for (int nt = 0; nt < 4; nt++) {
            const long row0 = (long)(m0 + warpM * 64 + mt * 16 + g);
            const int col = n0 + warpN * 32 + nt * 8 + l4 * 2;
            if (OUTH) {
                __half* Ch = (__half*)Cv;
                *(uint32_t*)&Ch[row0 * N + col] = pack_h2(c[mt][nt][0], c[mt][nt][1]);
                *(uint32_t*)&Ch[(row0 + 8) * N + col] = pack_h2(c[mt][nt][2], c[mt][nt][3]);
            } else {
                float* Cf = (float*)Cv;
                *(float2*)&Cf[row0 * N + col] = make_float2(c[mt][nt][0], c[mt][nt][1]);
                *(float2*)&Cf[(row0 + 8) * N + col] = make_float2(c[mt][nt][2], c[mt][nt][3]);
            }
        }
    }
}

// ---------------------------------------------------------------------------
// Prep kernels
// ---------------------------------------------------------------------------
// x fp32 -> fp16 (RN), 8 elements per thread
__global__ void cvt_f2h(const float* __restrict__ in, __half* __restrict__ out, int n8)
{
    int i = blockIdx.x * blockDim.x + threadIdx.x;
    if (i < n8) {
        float4 a = ((const float4*)in)[2 * i];
        float4 b = ((const float4*)in)[2 * i + 1];
        uint4 o;
        o.x = pack_h2(a.x, a.y); o.y = pack_h2(a.z, a.w);
        o.z = pack_h2(b.x, b.y); o.w = pack_h2(b.z, b.w);
        ((uint4*)out)[i] = o;
    }
}

// weights: in fp32 [R][C] -> out fp16 [C][R]
__global__ void transpose_h(const float* __restrict__ in, __half* __restrict__ out,
                            int R, int C)
{
    __shared__ float tile[32][33];
    const int c0 = blockIdx.x * 32, r0 = blockIdx.y * 32;
    const int tx = threadIdx.x, ty = threadIdx.y;
    #pragma unroll
    for (int j = ty; j < 32; j += 8)
        tile[j][tx] = in[(long)(r0 + j) * C + c0 + tx];
    __syncthreads();
    #pragma unroll
    for (int j = ty; j < 32; j += 8)
        out[(long)(c0 + j) * R + r0 + tx] = __float2half_rn(tile[tx][j]);
}

// V slice of qkv (half) -> vt[b][h][d][s] (half), via 4B-slot shared tile
__global__ void transpose_v(const __half* __restrict__ qkv, __half* __restrict__ vt)
{
    __shared__ uint32_t tile[32][33];
    const int bh = blockIdx.z;
    const int b = bh / NHEAD, hh = bh % NHEAD;
    const __half* in = qkv + (long)b * SEQ * QKV3 + 2 * HID + hh * HDIM;
    __half* out = vt + (long)bh * HDIM * SEQ;
    const int c0 = blockIdx.x * 32, r0 = blockIdx.y * 32;   // c: dim, r: seq
    const int tx = threadIdx.x, ty = threadIdx.y;
    #pragma unroll
    for (int j = ty; j < 32; j += 8)
        tile[j][tx] = __half_as_ushort(in[(long)(r0 + j) * QKV3 + c0 + tx]);
    __syncthreads();
    #pragma unroll
    for (int j = ty; j < 32; j += 8)
        out[(long)(c0 + j) * SEQ + r0 + tx] = __ushort_as_half((unsigned short)tile[tx][j]);
}

// ---------------------------------------------------------------------------
// Flash attention (causal) on fp16 mma.sync.
// 256 threads / 8 warps; warp w owns 16 q-rows of the 128-row tile.
// K tile [64 keys][72h]; Vt tile [64 dims][72h]; P/Q staged [128][72h].
// All pitches 144B -> conflict-free ldmatrix. SMEM 54KB -> 2 CTAs/SM.
// ---------------------------------------------------------------------------
#define FQT 128
#define FKT 64
#define KS_OFF(s)  ((s) * 9216)
#define VS_OFF(s)  (18432 + (s) * 9216)
#define PS_OFF     36864
#define FLASH_SMEM_BYTES (PS_OFF + 128 * 144)   // 55296
#define SC2 0.1803368801f   // (1/sqrt(64)) * log2(e)

__global__ __launch_bounds__(256, 2)
void flash_f16(const __half* __restrict__ qkv, const __half* __restrict__ vt,
               __half* __restrict__ out)
{
    extern __shared__ char sm[];
    const uint32_t sb = smem_u32(sm);
    const int tid = threadIdx.x, w = tid >> 5, lane = tid & 31;
    const int g = lane >> 2, l4 = lane & 3;
    const int qt = (int)(gridDim.x - 1) - (int)blockIdx.x;   // heavy blocks first
    const int hh = blockIdx.y, b = blockIdx.z;
    const int q0 = qt * FQT;
    const int nkv = 2 * qt + 2;

    const __half* qg = qkv + (long)b * SEQ * QKV3 + hh * HDIM;
    const __half* kg = qg + HID;
    const __half* vtg = vt + (long)(b * NHEAD + hh) * HDIM * SEQ;

    const int rlm = lane & 15, half_ = (lane >> 4) * 16;
    const int nr = lane & 7, sel = ((lane >> 3) & 1) * 16;

    // --- Stage Q into PS region [128 rows][144B] (each row = 64 halves) ---
    {
        const int r = tid >> 1, h2 = tid & 1;
        const __half* src = qg + (long)(q0 + r) * QKV3 + h2 * 32;
        uint32_t dst = sb + PS_OFF + (uint32_t)(r * 144 + h2 * 64);
        #pragma unroll
        for (int q = 0; q < 4; q++) cp16(dst + q * 16, src + q * 8);
        cp_commit();
    }
    cp_wait0();
    __syncthreads();

    // --- Q fragments: 4 k16 steps ---
    uint32_t qa[4][4];
    #pragma unroll
    for (int ks = 0; ks < 4; ks++)
        ldsm4(qa[ks], sb + PS_OFF + (uint32_t)((w * 16 + rlm) * 144) + ks * 32 + half_);
    __syncthreads();

    // KV loader: 64 rows x 128B each tile; 256 threads -> 32B (2 cp16) per tile
    auto issue_kv = [&](int kt2, int s) {
        const int k0 = kt2 * FKT;
        const int r = tid >> 2, q4 = tid & 3;
        const __half* ksrc = kg + (long)(k0 + r) * QKV3 + q4 * 16;
        uint32_t kdst = sb + KS_OFF(s) + (uint32_t)(r * 144 + q4 * 32);
        cp16(kdst, ksrc);
        cp16(kdst + 16, ksrc + 8);
        const __half* vsrc = vtg + (long)r * SEQ + k0 + q4 * 16;   // r = dim
        uint32_t vdst = sb + VS_OFF(s) + (uint32_t)(r * 144 + q4 * 32);
        cp16(vdst, vsrc);
        cp16(vdst + 16, vsrc + 8);
    };

    issue_kv(0, 0); cp_commit();
    if (nkv > 1) issue_kv(1, 1);
    cp_commit();

    float mA = -1e30f, mB = -1e30f, lA = 0.f, lB = 0.f;
    float o[8][4];
    #pragma unroll
    for (int nt = 0; nt < 8; nt++)
        #pragma unroll
        for (int q = 0; q < 4; q++) o[nt][q] = 0.f;

    const int wrow0 = q0 + w * 16;

    #pragma unroll 1
    for (int kt = 0; kt < nkv; kt++) {
        const int s = kt & 1;
        if (kt + 2 < nkv) cp_wait1(); else cp_wait0();
        __syncthreads();

        const int k0 = kt * FKT;
        const bool active = (k0 <= wrow0 + 15);
        const bool needmask = (k0 + FKT - 1 > wrow0);

        if (active) {
            const uint32_t kb = sb + KS_OFF(s);
            const uint32_t vb = sb + VS_OFF(s);

            float cc[8][4];
            #pragma unroll
            for (int nt = 0; nt < 8; nt++)
                #pragma unroll
                for (int q = 0; q < 4; q++) cc[nt][q] = 0.f;

            // S = Q @ K^T : B-frags ldsm2 from K [keys][dims]
            #pragma unroll
            for (int ks = 0; ks < 4; ks++) {
                uint32_t bfr[8][2];
                #pragma unroll
                for (int nt = 0; nt < 8; nt++)
                    ldsm2(bfr[nt], kb + (uint32_t)((nt * 8 + nr) * 144) + ks * 32 + sel);
                #pragma unroll
                for (int nt = 0; nt < 8; nt++)
                    mma_f16(cc[nt], qa[ks], bfr[nt]);
            }

            const int rowA = wrow0 + g;
            if (needmask) {
                #pragma unroll
                for (int nt = 0; nt < 8; nt++) {
                    const int colb = k0 + nt * 8 + 2 * l4;
                    if (colb     > rowA)     cc[nt][0] = -1e30f;
                    if (colb + 1 > rowA)     cc[nt][1] = -1e30f;
                    if (colb     > rowA + 8) cc[nt][2] = -1e30f;
                    if (colb + 1 > rowA + 8) cc[nt][3] = -1e30f;
                }
            }

            float mxA = -1e30f, mxB = -1e30f;
            #pragma unroll
            for (int nt = 0; nt < 8; nt++) {
                mxA = fmaxf(mxA, fmaxf(cc[nt][0], cc[nt][1]));
                mxB = fmaxf(mxB, fmaxf(cc[nt][2], cc[nt][3]));
            }
            mxA = fmaxf(mxA, __shfl_xor_sync(0xffffffffu, mxA, 1));
            mxA = fmaxf(mxA, __shfl_xor_sync(0xffffffffu, mxA, 2));
            mxB = fmaxf(mxB, __shfl_xor_sync(0xffffffffu, mxB, 1));
            mxB = fmaxf(mxB, __shfl_xor_sync(0xffffffffu, mxB, 2));

            const float mAn = fmaxf(mA, mxA);
            const float mBn = fmaxf(mB, mxB);
            const float aAl = ex2f((mA - mAn) * SC2);
            const float aBl = ex2f((mB - mBn) * SC2);
            mA = mAn; mB = mBn;

            float sA = 0.f, sB = 0.f;
            const uint32_t pbase = sb + PS_OFF + (uint32_t)((w * 16 + g) * 144 + l4 * 4);
            #pragma unroll
            for (int nt = 0; nt < 8; nt++) {
                float p0 = ex2f((cc[nt][0] - mAn) * SC2);
                float p1 = ex2f((cc[nt][1] - mAn) * SC2);
                float p2 = ex2f((cc[nt][2] - mBn) * SC2);
                float p3 = ex2f((cc[nt][3] - mBn) * SC2);
                sA += p0 + p1; sB += p2 + p3;
                sts32(pbase + nt * 16, pack_h2(p0, p1));
                sts32(pbase + nt * 16 + 8 * 144, pack_h2(p2, p3));
            }
            sA += __shfl_xor_sync(0xffffffffu, sA, 1);
            sA += __shfl_xor_sync(0xffffffffu, sA, 2);
            sB += __shfl_xor_sync(0xffffffffu, sB, 1);
            sB += __shfl_xor_sync(0xffffffffu, sB, 2);
            lA = lA * aAl + sA;
            lB = lB * aBl + sB;

            #pragma unroll
            for (int nt = 0; nt < 8; nt++) {
                o[nt][0] *= aAl; o[nt][1] *= aAl;
                o[nt][2] *= aBl; o[nt][3] *= aBl;
            }
            __syncwarp();

            // O += P @ V : A-frags ldsm4 from P, B-frags ldsm2 from Vt [dims][keys]
            #pragma unroll
            for (int ks = 0; ks < 4; ks++) {
                uint32_t pa[4];
                ldsm4(pa, sb + PS_OFF + (uint32_t)((w * 16 + rlm) * 144) + ks * 32 + half_);
                uint32_t bv[8][2];
                #pragma unroll
                for (int nt = 0; nt < 8; nt++)
                    ldsm2(bv[nt], vb + (uint32_t)((nt * 8 + nr) * 144) + ks * 32 + sel);
                #pragma unroll
                for (int nt = 0; nt < 8; nt++)
                    mma_f16(o[nt], pa, bv[nt]);
            }
        }

        __syncthreads();
        if (kt + 2 < nkv) { issue_kv(kt + 2, s); cp_commit(); }
    }

    // Epilogue: normalize, write half [B,S,H]
    {
        const float invA = 1.f / lA;
        const float invB = 1.f / lB;
        const long rowA = (long)b * SEQ + q0 + w * 16 + g;
        #pragma unroll
        for (int nt = 0; nt < 8; nt++) {
            const int col = hh * HDIM + nt * 8 + 2 * l4;
            *(uint32_t*)&out[rowA * HID + col] = pack_h2(o[nt][0] * invA, o[nt][1] * invA);
            *(uint32_t*)&out[(rowA + 8) * HID + col] = pack_h2(o[nt][2] * invB, o[nt][3] * invB);
        }
    }
}

// ---------------------------------------------------------------------------
// Launch
// ---------------------------------------------------------------------------
extern "C" void kernel_launch(void* const* d_in, const int* in_sizes, int n_in,
                              void* d_out, int out_size)
{
    const float* x     = (const float*)d_in[0];
    const float* w_qkv = (const float*)d_in[1];
    const float* w_out = (const float*)d_in[2];
    float* out = (float*)d_out;

    __half *xh, *qkvh, *attnh, *wqkvT, *woutT, *vt;
    cudaGetSymbolAddress((void**)&xh, g_xh);
    cudaGetSymbolAddress((void**)&qkvh, g_qkvh);
    cudaGetSymbolAddress((void**)&attnh, g_attnh);
    cudaGetSymbolAddress((void**)&wqkvT, g_wqkvT);
    cudaGetSymbolAddress((void**)&woutT, g_woutT);
    cudaGetSymbolAddress((void**)&vt, g_vt);

    const int M = BATCH * SEQ;   // 8192

    // 0) prep: x -> fp16; weights -> fp16 transposed [N][K]
    {
        int n8 = (M * HID) / 8;
        cvt_f2h<<<(n8 + 255) / 256, 256>>>(x, xh, n8);
        transpose_h<<<dim3(QKV3 / 32, KDIM / 32), dim3(32, 8)>>>(w_qkv, wqkvT,
                                                                 KDIM, QKV3);
        transpose_h<<<dim3(HID / 32, KDIM / 32), dim3(32, 8)>>>(w_out, woutT,
                                                                KDIM, HID);
    }

    cudaFuncSetAttribute(gemm_f16<true>,
                         cudaFuncAttributeMaxDynamicSharedMemorySize, GEMM_SMEM_BYTES);
    cudaFuncSetAttribute(gemm_f16<false>,
                         cudaFuncAttributeMaxDynamicSharedMemorySize, GEMM_SMEM_BYTES);
    cudaFuncSetAttribute(flash_f16,
                         cudaFuncAttributeMaxDynamicSharedMemorySize, FLASH_SMEM_BYTES);

    // 1) QKV projection (half output)
    gemm_f16<true><<<dim3(QKV3 / 128, M / 128), 256, GEMM_SMEM_BYTES>>>(
        xh, wqkvT, qkvh, M, QKV3, KDIM);

    // 1b) V -> vt[b][h][d][s]
    transpose_v<<<dim3(HDIM / 32, SEQ / 32, BATCH * NHEAD), dim3(32, 8)>>>(qkvh, vt);

    // 2) Causal flash attention (half in/out)
    flash_f16<<<dim3(SEQ / FQT, NHEAD, BATCH), 256, FLASH_SMEM_BYTES>>>(qkvh, vt, attnh);

    // 3) Output projection (float output)
    gemm_f16<false><<<dim3(HID / 128, M / 128), 256, GEMM_SMEM_BYTES>>>(
        attnh, woutT, out, M, HID, KDIM);
}